// round 17
// baseline (speedup 1.0000x reference)
#include <cuda_runtime.h>
#include <cuda_fp16.h>
#include <math.h>

// ---------------- problem constants ----------------
#define D_MODEL 512
#define HEADS   8
#define DK      64
#define N_LAYERS 4
#define BS      16
#define SEQ     4096
#define EPS     1e-6f
#define ROWS    (BS * SEQ)              // 65536
#define INV_SQRT_DK 0.125f
#define PBLK    (SEQ / 8)               // 512 partial blocks per batch
#define DD      (D_MODEL * D_MODEL)

typedef unsigned long long ull;

// ---------------- scratch (device globals; device-code access ONLY) ----------
__device__ __half g_yh[(size_t)ROWS * D_MODEL];   // norm1 out hi
__device__ __half g_yl[(size_t)ROWS * D_MODEL];   // norm1 out lo
__device__ __half g_v [(size_t)ROWS * D_MODEL];   // v projection (fp16)
__device__ __half g_rh[(size_t)ROWS * D_MODEL];   // relu-out hi
__device__ __half g_rl[(size_t)ROWS * D_MODEL];   // relu-out lo
__device__ float g_part[(size_t)BS * PBLK * D_MODEL];   // colsum partials (16MB)
__device__ float g_ksum[BS * D_MODEL];
__device__ float g_M[(size_t)BS * HEADS * DK * DK];
// W~_b hi/lo (per batch, current layer)
__device__ __half g_Wth[(size_t)BS * DD];
__device__ __half g_Wtl[(size_t)BS * DD];
// pre-split fp16 Wv (hi/lo), all layers
__device__ __half g_Wvh[(size_t)N_LAYERS * DD];
__device__ __half g_Wvl[(size_t)N_LAYERS * DD];

// ---------------- helpers -----------------------------------------------------
__device__ __forceinline__ void hsplit(float v, __half& h, __half& l) {
    h = __float2half_rn(v);
    l = __float2half_rn(v - __half2float(h));
}
__device__ __forceinline__ unsigned hpack2(__half a, __half b) {
    __half2 p = __halves2half2(a, b);
    return *reinterpret_cast<unsigned*>(&p);
}
__device__ __forceinline__ uint2 hpack4(__half a, __half b, __half c, __half d) {
    uint2 u;
    u.x = hpack2(a, b);
    u.y = hpack2(c, d);
    return u;
}
__device__ __forceinline__ unsigned smem_u32(const void* p) {
    unsigned a;
    asm("{ .reg .u64 t; cvta.to.shared.u64 t, %1; cvt.u32.u64 %0, t; }"
        : "=r"(a) : "l"(p));
    return a;
}
__device__ __forceinline__ void mma16816(float* c, const unsigned* a, const unsigned* b) {
    asm volatile(
        "mma.sync.aligned.m16n8k16.row.col.f32.f16.f16.f32 "
        "{%0,%1,%2,%3}, {%4,%5,%6,%7}, {%8,%9}, {%0,%1,%2,%3};"
        : "+f"(c[0]), "+f"(c[1]), "+f"(c[2]), "+f"(c[3])
        : "r"(a[0]), "r"(a[1]), "r"(a[2]), "r"(a[3]), "r"(b[0]), "r"(b[1]));
}
__device__ __forceinline__ void ldsm4(unsigned* r, unsigned addr) {
    asm volatile("ldmatrix.sync.aligned.m8n8.x4.shared.b16 {%0,%1,%2,%3}, [%4];"
                 : "=r"(r[0]), "=r"(r[1]), "=r"(r[2]), "=r"(r[3]) : "r"(addr));
}
__device__ __forceinline__ void cp_async16(unsigned dst, const void* src) {
    asm volatile("cp.async.cg.shared.global [%0], [%1], 16;" :: "r"(dst), "l"(src));
}
__device__ __forceinline__ void cp_commit() {
    asm volatile("cp.async.commit_group;" ::: "memory");
}
template <int N>
__device__ __forceinline__ void cp_wait() {
    asm volatile("cp.async.wait_group %0;" :: "n"(N) : "memory");
}

__device__ __forceinline__ void row_stats(const float4* v, float& mean, float& r) {
    float s = 0.f, ss = 0.f;
    #pragma unroll
    for (int i = 0; i < 4; i++) {
        s  += v[i].x + v[i].y + v[i].z + v[i].w;
        ss += v[i].x * v[i].x + v[i].y * v[i].y + v[i].z * v[i].z + v[i].w * v[i].w;
    }
    #pragma unroll
    for (int o = 16; o > 0; o >>= 1) {
        s  += __shfl_xor_sync(0xffffffffu, s,  o);
        ss += __shfl_xor_sync(0xffffffffu, ss, o);
    }
    mean = s * (1.0f / D_MODEL);
    float var = (ss - (float)D_MODEL * mean * mean) * (1.0f / (D_MODEL - 1));
    var = fmaxf(var, 0.0f);
    r = 1.0f / (sqrtf(var) + EPS);
}

// deterministic per-block column sums of the 8 rows' y values -> g_part
// sm: [8][512] floats (16KB). Each warp wrote its row; then 256 threads reduce.
__device__ __forceinline__ void emit_colsum_partials(float (*sm)[D_MODEL],
                                                     int bx, int tid)
{
    __syncthreads();
    int batch = bx >> 9;            // 512 blocks per batch
    int p     = bx & (PBLK - 1);
    float* dst = g_part + ((size_t)batch * PBLK + p) * D_MODEL;
    #pragma unroll
    for (int t = 0; t < 2; t++) {
        int c = tid + t * 256;
        float s = 0.f;
        #pragma unroll
        for (int r = 0; r < 8; r++) s += sm[r][c];
        dst[c] = s;
    }
}

// ---------------- norm kernels (warp-per-row, 8 rows/CTA) ----------------------
// layer 0: y = norm1(x) -> yh/yl + colsum partials
__global__ __launch_bounds__(256)
void norm_first_kernel(const float* __restrict__ ext_in,
                       const float* __restrict__ alpha,
                       const float* __restrict__ beta)
{
    __shared__ float sm[8][D_MODEL];
    int tid = threadIdx.x, lane = tid & 31, wrp = tid >> 5;
    size_t row = (size_t)blockIdx.x * 8 + wrp;
    const float4* rp = (const float4*)(ext_in + row * D_MODEL);
    float4 v[4];
    #pragma unroll
    for (int i = 0; i < 4; i++) v[i] = rp[lane + 32 * i];
    float mean, r;
    row_stats(v, mean, r);
    #pragma unroll
    for (int i = 0; i < 4; i++) {
        int c4 = lane + 32 * i;
        float4 a4 = ((const float4*)alpha)[c4];
        float4 b4 = ((const float4*)beta)[c4];
        float o0 = a4.x * (v[i].x - mean) * r + b4.x;
        float o1 = a4.y * (v[i].y - mean) * r + b4.y;
        float o2 = a4.z * (v[i].z - mean) * r + b4.z;
        float o3 = a4.w * (v[i].w - mean) * r + b4.w;
        *(float4*)&sm[wrp][c4 * 4] = make_float4(o0, o1, o2, o3);
        __half h0, h1, h2, h3, l0, l1, l2, l3;
        hsplit(o0, h0, l0); hsplit(o1, h1, l1);
        hsplit(o2, h2, l2); hsplit(o3, h3, l3);
        ((uint2*)(g_yh + row * D_MODEL))[c4] = hpack4(h0, h1, h2, h3);
        ((uint2*)(g_yl + row * D_MODEL))[c4] = hpack4(l0, l1, l2, l3);
    }
    emit_colsum_partials(sm, blockIdx.x, tid);
}

// mid layers: z = y + r; t = norm2(z); y' = norm1(t) -> yh/yl + partials
__global__ __launch_bounds__(256)
void norm_mid_kernel(const float* __restrict__ a2, const float* __restrict__ b2,
                     const float* __restrict__ a1, const float* __restrict__ b1)
{
    __shared__ float sm[8][D_MODEL];
    int tid = threadIdx.x, lane = tid & 31, wrp = tid >> 5;
    size_t row = (size_t)blockIdx.x * 8 + wrp;
    float4 v[4];
    #pragma unroll
    for (int i = 0; i < 4; i++) {
        int c4 = lane + 32 * i;
        uint2 yhu = ((const uint2*)(g_yh + row * D_MODEL))[c4];
        uint2 ylu = ((const uint2*)(g_yl + row * D_MODEL))[c4];
        uint2 rhu = ((const uint2*)(g_rh + row * D_MODEL))[c4];
        uint2 rlu = ((const uint2*)(g_rl + row * D_MODEL))[c4];
        float2 yh0 = __half22float2(*(__half2*)&yhu.x);
        float2 yh1 = __half22float2(*(__half2*)&yhu.y);
        float2 yl0 = __half22float2(*(__half2*)&ylu.x);
        float2 yl1 = __half22float2(*(__half2*)&ylu.y);
        float2 rh0 = __half22float2(*(__half2*)&rhu.x);
        float2 rh1 = __half22float2(*(__half2*)&rhu.y);
        float2 rl0 = __half22float2(*(__half2*)&rlu.x);
        float2 rl1 = __half22float2(*(__half2*)&rlu.y);
        v[i].x = (yh0.x + yl0.x) + (rh0.x + rl0.x);
        v[i].y = (yh0.y + yl0.y) + (rh0.y + rl0.y);
        v[i].z = (yh1.x + yl1.x) + (rh1.x + rl1.x);
        v[i].w = (yh1.y + yl1.y) + (rh1.y + rl1.y);
    }
    float mean, r;
    row_stats(v, mean, r);
    #pragma unroll
    for (int i = 0; i < 4; i++) {
        int c4 = lane + 32 * i;
        float4 a4 = ((const float4*)a2)[c4];
        float4 b4 = ((const float4*)b2)[c4];
        v[i].x = a4.x * (v[i].x - mean) * r + b4.x;
        v[i].y = a4.y * (v[i].y - mean) * r + b4.y;
        v[i].z = a4.z * (v[i].z - mean) * r + b4.z;
        v[i].w = a4.w * (v[i].w - mean) * r + b4.w;
    }
    row_stats(v, mean, r);
    #pragma unroll
    for (int i = 0; i < 4; i++) {
        int c4 = lane + 32 * i;
        float4 a4 = ((const float4*)a1)[c4];
        float4 b4 = ((const float4*)b1)[c4];
        float o0 = a4.x * (v[i].x - mean) * r + b4.x;
        float o1 = a4.y * (v[i].y - mean) * r + b4.y;
        float o2 = a4.z * (v[i].z - mean) * r + b4.z;
        float o3 = a4.w * (v[i].w - mean) * r + b4.w;
        *(float4*)&sm[wrp][c4 * 4] = make_float4(o0, o1, o2, o3);
        __half h0, h1, h2, h3, l0, l1, l2, l3;
        hsplit(o0, h0, l0); hsplit(o1, h1, l1);
        hsplit(o2, h2, l2); hsplit(o3, h3, l3);
        ((uint2*)(g_yh + row * D_MODEL))[c4] = hpack4(h0, h1, h2, h3);
        ((uint2*)(g_yl + row * D_MODEL))[c4] = hpack4(l0, l1, l2, l3);
    }
    emit_colsum_partials(sm, blockIdx.x, tid);
}

// last layer: out = norm2(y + r)  (fp32)
__global__ __launch_bounds__(256)
void norm_last_kernel(const float* __restrict__ alpha,
                      const float* __restrict__ beta,
                      float* __restrict__ out)
{
    int tid = threadIdx.x, lane = tid & 31, wrp = tid >> 5;
    size_t row = (size_t)blockIdx.x * 8 + wrp;
    float4 v[4];
    #pragma unroll
    for (int i = 0; i < 4; i++) {
        int c4 = lane + 32 * i;
        uint2 yhu = ((const uint2*)(g_yh + row * D_MODEL))[c4];
        uint2 ylu = ((const uint2*)(g_yl + row * D_MODEL))[c4];
        uint2 rhu = ((const uint2*)(g_rh + row * D_MODEL))[c4];
        uint2 rlu = ((const uint2*)(g_rl + row * D_MODEL))[c4];
        float2 yh0 = __half22float2(*(__half2*)&yhu.x);
        float2 yh1 = __half22float2(*(__half2*)&yhu.y);
        float2 yl0 = __half22float2(*(__half2*)&ylu.x);
        float2 yl1 = __half22float2(*(__half2*)&ylu.y);
        float2 rh0 = __half22float2(*(__half2*)&rhu.x);
        float2 rh1 = __half22float2(*(__half2*)&rhu.y);
        float2 rl0 = __half22float2(*(__half2*)&rlu.x);
        float2 rl1 = __half22float2(*(__half2*)&rlu.y);
        v[i].x = (yh0.x + yl0.x) + (rh0.x + rl0.x);
        v[i].y = (yh0.y + yl0.y) + (rh0.y + rl0.y);
        v[i].z = (yh1.x + yl1.x) + (rh1.x + rl1.x);
        v[i].w = (yh1.y + yl1.y) + (rh1.y + rl1.y);
    }
    float mean, r;
    row_stats(v, mean, r);
    #pragma unroll
    for (int i = 0; i < 4; i++) {
        int c4 = lane + 32 * i;
        float4 a4 = ((const float4*)alpha)[c4];
        float4 b4 = ((const float4*)beta)[c4];
        float4 o4;
        o4.x = a4.x * (v[i].x - mean) * r + b4.x;
        o4.y = a4.y * (v[i].y - mean) * r + b4.y;
        o4.z = a4.z * (v[i].z - mean) * r + b4.z;
        o4.w = a4.w * (v[i].w - mean) * r + b4.w;
        ((float4*)(out + row * D_MODEL))[c4] = o4;
    }
}

// ---------------- ksum: reduce 512 partials per (batch, col) --------------------
__global__ void ksum_reduce_kernel()
{
    int b  = blockIdx.x >> 1;
    int cb = blockIdx.x & 1;
    int c  = cb * 256 + threadIdx.x;
    const float* src = g_part + (size_t)b * PBLK * D_MODEL + c;
    float s = 0.f;
    #pragma unroll 4
    for (int p = 0; p < PBLK; p++)
        s += src[(size_t)p * D_MODEL];
    g_ksum[b * D_MODEL + c] = s;
}

// ---------------- scores: M = softmax + I ---------------------------------------
__global__ void scores_kernel(const float* __restrict__ convw,
                              const float* __restrict__ convb)
{
    __shared__ float ks[DK];
    int bh = blockIdx.x;
    int b = bh / HEADS, h = bh % HEADS;
    int c = threadIdx.x;
    ks[c] = g_ksum[b * D_MODEL + h * DK + c];
    __syncthreads();

    float w  = convw[c] * INV_SQRT_DK;
    float bb = (float)SEQ * convb[c] * INV_SQRT_DK;

    float logit[DK];
    float mx = -1e30f;
    #pragma unroll
    for (int j = 0; j < DK; j++) {
        logit[j] = fmaf(w, ks[j], bb);
        mx = fmaxf(mx, logit[j]);
    }
    float sum = 0.f;
    #pragma unroll
    for (int j = 0; j < DK; j++) {
        logit[j] = expf(logit[j] - mx);
        sum += logit[j];
    }
    float inv = 1.0f / sum;
    float* Mp = g_M + (size_t)bh * DK * DK;
    #pragma unroll
    for (int j = 0; j < DK; j++)
        Mp[j * DK + c] = logit[j] * inv + (j == c ? 1.0f : 0.0f);
}

// ---------------- W~ build ------------------------------------------------------
__global__ __launch_bounds__(256)
void make_wt_kernel(const float* __restrict__ Wo)
{
    __shared__ float Ms[DK][DK + 1];
    int bh = blockIdx.x;
    int b = bh >> 3, h = bh & 7;
    int tid = threadIdx.x;

    #pragma unroll
    for (int t = 0; t < 16; t++) {
        int lin = tid + 256 * t;
        Ms[lin >> 6][lin & 63] = g_M[(size_t)bh * DK * DK + lin];
    }
    __syncthreads();

    int j  = tid & 63;
    int og = tid >> 6;
    #pragma unroll 1
    for (int ob = 0; ob < 8; ob++) {
        #pragma unroll 1
        for (int i = 0; i < 16; i++) {
            int o = ob * 64 + og * 16 + i;
            const float4* wrow = (const float4*)(Wo + (size_t)o * D_MODEL + h * DK);
            float s = 0.f;
            #pragma unroll
            for (int c4 = 0; c4 < 16; c4++) {
                float4 w4 = wrow[c4];
                s += w4.x * Ms[j][c4 * 4 + 0] + w4.y * Ms[j][c4 * 4 + 1]
                   + w4.z * Ms[j][c4 * 4 + 2] + w4.w * Ms[j][c4 * 4 + 3];
            }
            __half hh, hl;
            hsplit(s, hh, hl);
            size_t wi = ((size_t)b * D_MODEL + o) * D_MODEL + h * DK + j;
            g_Wth[wi] = hh;
            g_Wtl[wi] = hl;
        }
    }
}

// ---------------- Wv split (all layers) -----------------------------------------
__global__ void convert_w_kernel(const float* __restrict__ Wv)
{
    size_t i = (size_t)blockIdx.x * 256 + threadIdx.x;
    __half h, l;
    hsplit(Wv[i], h, l);
    g_Wvh[i] = h;
    g_Wvl[i] = l;
}

// ---------------- GEMM geometry --------------------------------------------------
#define BK 32
#define NCHK (D_MODEL / BK)
#define RSTRIDE 80
#define TILE_B (128 * RSTRIDE)

// ---------------- GEMM0: v = y @ Wv^T + bv  (3-term, A = y hi/lo exact) ----------
#define A3_T_AH 0u
#define A3_T_AL ((unsigned)TILE_B)
#define A3_T_BH ((unsigned)(2 * TILE_B))
#define A3_T_BL ((unsigned)(3 * TILE_B))
#define A3_STAGE (4 * TILE_B)
#define A3_DYN (2 * A3_STAGE)

__global__ __launch_bounds__(256)
void gemm_a3_kernel(int layer, const float* __restrict__ bias)
{
    extern __shared__ __align__(16) char dyn[];
    const unsigned dynb = smem_u32(dyn);

    const size_t wofs = (size_t)layer * DD;
    const __half* Wh = g_Wvh + wofs;
    const __half* Wl = g_Wvl + wofs;

    const int tid  = threadIdx.x;
    const int lane = tid & 31;
    const int wid  = tid >> 5;
    const int bn   = blockIdx.x;
    const int bm   = blockIdx.y;
    const int wm   = (wid & 3) * 32;
    const int wn   = (wid >> 2) * 64;

    const size_t arow0 = (size_t)bm * 128;
    const size_t brow0 = (size_t)bn * 128;

    int ldRow[2], ldC[2];
    #pragma unroll
    for (int i = 0; i < 2; i++) {
        int lin = tid + i * 256;
        ldRow[i] = lin >> 2;
        ldC[i]   = lin & 3;
    }

    auto load_stage = [&](int chk, unsigned sb) {
        int k0 = chk * BK;
        #pragma unroll
        for (int i = 0; i < 2; i++) {
            unsigned so = (unsigned)(ldRow[i] * RSTRIDE + ldC[i] * 16);
            size_t ga = (arow0 + ldRow[i]) * D_MODEL + k0 + ldC[i] * 8;
            size_t gb = (brow0 + ldRow[i]) * D_MODEL + k0 + ldC[i] * 8;
            cp_async16(sb + A3_T_AH + so, g_yh + ga);
            cp_async16(sb + A3_T_AL + so, g_yl + ga);
            cp_async16(sb + A3_T_BH + so, Wh + gb);
            cp_async16(sb + A3_T_BL + so, Wl + gb);
        }
    };

    float acc[2][8][4];
    #pragma unroll
    for (int im = 0; im < 2; im++)
        #pragma unroll
        for (int in = 0; in < 8; in++)
            #pragma unroll
            for (int q = 0; q < 4; q++) acc[im][in][q] = 0.f;

    load_stage(0, dynb);
    cp_commit();
    load_stage(1, dynb + A3_STAGE);
    cp_commit();
    cp_wait<1>();
    __syncthreads();

    #pragma unroll 1
    for (int chk = 0; chk < NCHK; chk++) {
        const unsigned sb = dynb + (chk & 1) * A3_STAGE;

        #pragma unroll
        for (int ks = 0; ks < 2; ks++) {
            unsigned ah[2][4], al[2][4];
            #pragma unroll
            for (int im = 0; im < 2; im++) {
                int row = wm + im * 16 + (lane & 15);
                unsigned cA = (unsigned)(ks * 2 + (lane >> 4));
                unsigned ad = (unsigned)(row * RSTRIDE) + cA * 16u;
                ldsm4(ah[im], sb + A3_T_AH + ad);
                ldsm4(al[im], sb + A3_T_AL + ad);
            }
            #pragma unroll
            for (int g = 0; g < 4; g++) {
                unsigned bh[4], bl[4];
                int row = wn + g * 16 + ((lane >> 4) * 8) + (lane & 7);
                unsigned cB = (unsigned)(ks * 2 + ((lane >> 3) & 1));
                unsigned bd = (unsigned)(row * RSTRIDE) + cB * 16u;
                ldsm4(bh, sb + A3_T_BH + bd);
                ldsm4(bl, sb + A3_T_BL + bd);
                #pragma unroll
                for (int im = 0; im < 2; im++) {
                    mma16816(acc[im][2 * g],     ah[im], &bh[0]);
                    mma16816(acc[im][2 * g],     ah[im], &bl[0]);
                    mma16816(acc[im][2 * g],     al[im], &bh[0]);
                    mma16816(acc[im][2 * g + 1], ah[im], &bh[2]);
                    mma16816(acc[im][2 * g + 1], ah[im], &bl[2]);
                    mma16816(acc[im][2 * g + 1], al[im], &bh[2]);
                }
            }
        }
        __syncthreads();
        if (chk + 2 < NCHK) {
            load_stage(chk + 2, sb);
            cp_commit();
            cp_wait<1>();
        } else {
            cp_wait<0>();
        }
        __syncthreads();
    }

    #pragma unroll
    for (int im = 0; im < 2; im++) {
        int r0 = bm * 128 + wm + im * 16 + (lane >> 2);
        #pragma unroll
        for (int in = 0; in < 8; in++) {
            int col = bn * 128 + wn + in * 8 + (lane & 3) * 2;
            float bv0 = bias[col], bv1 = bias[col + 1];
            #pragma unroll
            for (int half = 0; half < 2; half++) {
                int row = r0 + half * 8;
                float v0 = acc[im][in][2 * half + 0] + bv0;
                float v1 = acc[im][in][2 * half + 1] + bv1;
                size_t gi = (size_t)row * D_MODEL + col;
                *(unsigned*)(g_v + gi) =
                    hpack2(__float2half_rn(v0), __float2half_rn(v1));
            }
        }
    }
}

// ---------------- GEMM1: r = relu(v @ W~_b^T + bo) -> rh/rl (2-term) -------------
#define B2_T_A  0u
#define B2_T_BH ((unsigned)TILE_B)
#define B2_T_BL ((unsigned)(2 * TILE_B))
#define B2_STAGE (3 * TILE_B)
#define B2_DYN (2 * B2_STAGE)

__global__ __launch_bounds__(256)
void gemm_b2_kernel(const float* __restrict__ bias)
{
    extern __shared__ __align__(16) char dyn[];
    const unsigned dynb = smem_u32(dyn);

    const int tid  = threadIdx.x;
    const int lane = tid & 31;
    const int wid  = tid >> 5;
    const int bn   = blockIdx.x;
    const int bm   = blockIdx.y;
    const int wm   = (wid & 3) * 32;
    const int wn   = (wid >> 2) * 64;

    const int batch = bm >> 5;
    const __half* Wh = g_Wth + (size_t)batch * DD;
    const __half* Wl = g_Wtl + (size_t)batch * DD;

    const size_t arow0 = (size_t)bm * 128;
    const size_t brow0 = (size_t)bn * 128;

    int ldRow[2], ldC[2];
    #pragma unroll
    for (int i = 0; i < 2; i++) {
        int lin = tid + i * 256;
        ldRow[i] = lin >> 2;
        ldC[i]   = lin & 3;
    }

    auto load_stage = [&](int chk, unsigned sb) {
        int k0 = chk * BK;
        #pragma unroll
        for (int i = 0; i < 2; i++) {
            unsigned so = (unsigned)(ldRow[i] * RSTRIDE + ldC[i] * 16);
            size_t ga = (arow0 + ldRow[i]) * D_MODEL + k0 + ldC[i] * 8;
            size_t gb = (brow0 + ldRow[i]) * D_MODEL + k0 + ldC[i] * 8;
            cp_async16(sb + B2_T_A  + so, g_v + ga);
            cp_async16(sb + B2_T_BH + so, Wh + gb);
            cp_async16(sb + B2_T_BL + so, Wl + gb);
        }
    };

    float acc[2][8][4];
    #pragma unroll
    for (int im = 0; im < 2; im++)
        #pragma unroll
        for (int in = 0; in < 8; in++)
            #pragma unroll
            for (int q = 0; q < 4; q++) acc[im][in][q] = 0.f;

    load_stage(0, dynb);
    cp_commit();
    load_stage(1, dynb + B2_STAGE);
    cp_commit();
    cp_wait<1>();
    __syncthreads();

    #pragma unroll 1
    for (int chk = 0; chk < NCHK; chk++) {
        const unsigned sb = dynb + (chk & 1) * B2_STAGE;

        #pragma unroll
        for (int ks = 0; ks < 2; ks++) {
            unsigned ah[2][4];
            #pragma unroll
            for (int im = 0; im < 2; im++) {
                int row = wm + im * 16 + (lane & 15);
                unsigned cA = (unsigned)(ks * 2 + (lane >> 4));
                unsigned ad = (unsigned)(row * RSTRIDE) + cA * 16u;
                ldsm4(ah[im], sb + B2_T_A + ad);
            }
            #pragma unroll
            for (int g = 0; g < 4; g++) {
                unsigned bh[4], bl[4];
                int row = wn + g * 16 + ((lane >> 4) * 8) + (lane & 7);
                unsigned cB = (unsigned)(ks * 2 + ((lane >> 3) & 1));
                unsigned bd = (unsigned)(row * RSTRIDE) + cB * 16u;
                ldsm4(bh, sb + B2_T_BH + bd);
                ldsm4(bl, sb + B2_T_BL + bd);
                #pragma unroll
                for (int im = 0; im < 2; im++) {
                    mma16816(acc[im][2 * g],     ah[im], &bh[0]);
                    mma16816(acc[im][2 * g],     ah[im], &bl[0]);
                    mma16816(acc[im][2 * g + 1], ah[im], &bh[2]);
                    mma16816(acc[im][2 * g + 1], ah[im], &bl[2]);
                }
            }
        }
        __syncthreads();
        if (chk + 2 < NCHK) {
            load_stage(chk + 2, sb);
            cp_commit();
            cp_wait<1>();
        } else {
            cp_wait<0>();
        }
        __syncthreads();
    }

    // epilogue: r = relu(acc + bias) -> exact fp16 hi/lo
    #pragma unroll
    for (int im = 0; im < 2; im++) {
        int r0 = bm * 128 + wm + im * 16 + (lane >> 2);
        #pragma unroll
        for (int in = 0; in < 8; in++) {
            int col = bn * 128 + wn + in * 8 + (lane & 3) * 2;
            float bv0 = bias[col], bv1 = bias[col + 1];
            #pragma unroll
            for (int half = 0; half < 2; half++) {
                int row = r0 + half * 8;
                float v0 = fmaxf(acc[im][in][2 * half + 0] + bv0, 0.0f);
                float v1 = fmaxf(acc[im][in][2 * half + 1] + bv1, 0.0f);
                size_t gi = (size_t)row * D_MODEL + col;
                __half h0, h1, l0, l1;
                hsplit(v0, h0, l0);
                hsplit(v1, h1, l1);
                *(unsigned*)(g_rh + gi) = hpack2(h0, h1);
                *(unsigned*)(g_rl + gi) = hpack2(l0, l1);
            }
        }
    }
}

// ---------------- driver ---------------------------------------------------------
extern "C" void kernel_launch(void* const* d_in, const int* in_sizes, int n_in,
                              void* d_out, int out_size)
{
    const float* x    = (const float*)d_in[0];
    const float* Wv   = (const float*)d_in[1];
    const float* bv   = (const float*)d_in[2];
    const float* cw   = (const float*)d_in[3];
    const float* cb   = (const float*)d_in[4];
    const float* Wo   = (const float*)d_in[5];
    const float* bo   = (const float*)d_in[6];
    const float* a1   = (const float*)d_in[7];
    const float* b1   = (const float*)d_in[8];
    const float* a2   = (const float*)d_in[9];
    const float* b2   = (const float*)d_in[10];
    float* out = (float*)d_out;

    cudaFuncSetAttribute(gemm_a3_kernel, cudaFuncAttributeMaxDynamicSharedMemorySize, A3_DYN);
    cudaFuncSetAttribute(gemm_b2_kernel, cudaFuncAttributeMaxDynamicSharedMemorySize, B2_DYN);

    convert_w_kernel<<<(N_LAYERS * DD) / 256, 256>>>(Wv);
    norm_first_kernel<<<ROWS / 8, 256>>>(x, a1, b1);   // y + colsum partials

    for (int L = 0; L < N_LAYERS; L++) {
        ksum_reduce_kernel<<<32, 256>>>();
        scores_kernel<<<BS * HEADS, 64>>>(cw + L * DK, cb + L * DK);
        make_wt_kernel<<<BS * HEADS, 256>>>(Wo + (size_t)L * DD);
        // v = y @ Wv^T + bv
        gemm_a3_kernel<<<dim3(4, 512), 256, A3_DYN>>>(L, bv + L * D_MODEL);
        // r = relu(v @ W~^T + bo)
        gemm_b2_kernel<<<dim3(4, 512), 256, B2_DYN>>>(bo + L * D_MODEL);
        // norms (+ colsum partials for next layer)
        if (L < N_LAYERS - 1) {
            norm_mid_kernel<<<ROWS / 8, 256>>>(a2 + L * D_MODEL, b2 + L * D_MODEL,
                                               a1 + (L + 1) * D_MODEL,
                                               b1 + (L + 1) * D_MODEL);
        } else {
            norm_last_kernel<<<ROWS / 8, 256>>>(a2 + L * D_MODEL, b2 + L * D_MODEL, out);
        }
    }
}